// round 1
// baseline (speedup 1.0000x reference)
#include <cuda_runtime.h>
#include <math.h>

// ---------------------------------------------------------------------------
// Problem constants
// ---------------------------------------------------------------------------
#define BB   64
#define SS   512
#define HID  256
#define NH   4
#define DH   64
#define MROWS (BB*SS)            // 32768
#define MAT   (MROWS*HID)        // 8388608 elements per [B,S,HID] tensor
#define NROW  (BB*NH*SS)         // 131072 head-rows

// ---------------------------------------------------------------------------
// Scratch (device globals: no allocation allowed)
// ---------------------------------------------------------------------------
__device__ float g_mq[MAT];
__device__ float g_mk[MAT];
__device__ float g_mv[MAT];
__device__ float g_sq[MAT];   // sqrt(clip(cq))
__device__ float g_sk[MAT];   // sqrt(clip(ck))
__device__ float g_cv[MAT];
__device__ float g_ctxm[MAT];
__device__ float g_ctxc[MAT];
__device__ float g_dm[MAT];
__device__ float g_dc[MAT];
__device__ float g_aq[NROW];
__device__ float g_ak[NROW];

// ---------------------------------------------------------------------------
// Fast exp (FFMA/ALU pipe; avoids MUFU bottleneck). |rel err| ~3e-6.
// Valid for x <= ~80; clamped below -87 -> ~0.
// ---------------------------------------------------------------------------
__device__ __forceinline__ float fexp(float x) {
    x = fmaxf(fminf(x, 80.f), -87.f);
    float y = x * 1.4426950408889634f;      // x * log2(e)
    int   i = __float2int_rn(y);
    float f = y - (float)i;
    float p = 1.3333558146e-3f;
    p = fmaf(p, f, 9.6181291918e-3f);
    p = fmaf(p, f, 5.5504108664e-2f);
    p = fmaf(p, f, 2.4022650696e-1f);
    p = fmaf(p, f, 6.9314718056e-1f);
    p = fmaf(p, f, 1.0f);
    return __int_as_float(__float_as_int(p) + (i << 23));
}

// ---------------------------------------------------------------------------
// GEMM: Y[M=32768, N=256] = X[M,256] @ W[256,256]^T + bias, w/ epilogue
//   ep=0: none ; ep=1: elu()+1 ; ep=2: sqrt(max(elu()+1, 1e-24))
// Classic 128x128x8 SGEMM, 256 threads, 8x8 micro-tile.
// ---------------------------------------------------------------------------
__global__ __launch_bounds__(256)
void gemm256(const float* __restrict__ X, const float* __restrict__ W,
             const float* __restrict__ bias, float* __restrict__ Y, int ep)
{
    __shared__ __align__(16) float As[8][128];
    __shared__ __align__(16) float Bs[8][128];
    const int tid = threadIdx.x;
    const int m0 = blockIdx.x * 128;
    const int n0 = blockIdx.y * 128;
    const int tx = tid & 15;
    const int ty = tid >> 4;
    const int lr = tid >> 1;           // 0..127
    const int lc = (tid & 1) * 4;      // 0 or 4

    float acc[8][8];
#pragma unroll
    for (int i = 0; i < 8; i++)
#pragma unroll
        for (int j = 0; j < 8; j++) acc[i][j] = 0.f;

    for (int k0 = 0; k0 < 256; k0 += 8) {
        float4 av = *(const float4*)(X + (size_t)(m0 + lr) * 256 + k0 + lc);
        float4 bv = *(const float4*)(W + (size_t)(n0 + lr) * 256 + k0 + lc);
        __syncthreads();
        As[lc + 0][lr] = av.x; As[lc + 1][lr] = av.y;
        As[lc + 2][lr] = av.z; As[lc + 3][lr] = av.w;
        Bs[lc + 0][lr] = bv.x; Bs[lc + 1][lr] = bv.y;
        Bs[lc + 2][lr] = bv.z; Bs[lc + 3][lr] = bv.w;
        __syncthreads();
#pragma unroll
        for (int kk = 0; kk < 8; kk++) {
            float a[8], b[8];
            *(float4*)(&a[0]) = *(const float4*)(&As[kk][ty * 8]);
            *(float4*)(&a[4]) = *(const float4*)(&As[kk][ty * 8 + 4]);
            *(float4*)(&b[0]) = *(const float4*)(&Bs[kk][tx * 8]);
            *(float4*)(&b[4]) = *(const float4*)(&Bs[kk][tx * 8 + 4]);
#pragma unroll
            for (int i = 0; i < 8; i++)
#pragma unroll
                for (int j = 0; j < 8; j++)
                    acc[i][j] = fmaf(a[i], b[j], acc[i][j]);
        }
    }

#pragma unroll
    for (int i = 0; i < 8; i++) {
        const int m = m0 + ty * 8 + i;
        float v[8];
#pragma unroll
        for (int j = 0; j < 8; j++) {
            float t = acc[i][j] + bias[n0 + tx * 8 + j];
            if (ep >= 1) t = (t > 0.f) ? (t + 1.f) : __expf(t);
            if (ep == 2) t = sqrtf(fmaxf(t, 1e-24f));
            v[j] = t;
        }
        float* yrow = Y + (size_t)m * 256 + n0 + tx * 8;
        *(float4*)(yrow)     = *(float4*)(&v[0]);
        *(float4*)(yrow + 4) = *(float4*)(&v[4]);
    }
}

// ---------------------------------------------------------------------------
// Row scalars:  A[(b*4+h)*512+s] = sum_d  M^2 + Sq^2  over the head slice
// One warp per row.
// ---------------------------------------------------------------------------
__global__ __launch_bounds__(256)
void rowsum_kernel(const float* __restrict__ M, const float* __restrict__ Sq,
                   float* __restrict__ A)
{
    const int w    = (blockIdx.x * blockDim.x + threadIdx.x) >> 5; // row id
    const int lane = threadIdx.x & 31;
    const int s  = w & 511;
    const int bh = w >> 9;            // b*4+h
    const int b  = bh >> 2, h = bh & 3;
    const int base = ((b * 512 + s) * 256) + h * 64;
    float vm0 = M[base + lane],      vm1 = M[base + 32 + lane];
    float vs0 = Sq[base + lane],     vs1 = Sq[base + 32 + lane];
    float sum = vm0 * vm0 + vm1 * vm1 + vs0 * vs0 + vs1 * vs1;
#pragma unroll
    for (int o = 16; o; o >>= 1) sum += __shfl_xor_sync(~0u, sum, o);
    if (!lane) A[w] = sum;
}

// ---------------------------------------------------------------------------
// Attention: one block = (b, h, 64-query tile). 256 threads.
// smem: Qs[128][68] (transposed [mq|sq]), Ks[128][68] (K tiles, reused for V),
//       Ssc[64][516] score rows, aq/ak/invz scalars.  ~200 KB dynamic smem.
// ---------------------------------------------------------------------------
#define QK_STR 68
#define SC_STR 516
#define ATT_SMEM_FLOATS (128*QK_STR*2 + 64*SC_STR + 64 + 512 + 64)
#define ATT_SMEM_BYTES  (ATT_SMEM_FLOATS * 4)

__global__ __launch_bounds__(256)
void attn_kernel(const float* __restrict__ mask, float* __restrict__ probs)
{
    extern __shared__ __align__(16) float sm[];
    float* Qs    = sm;                         // 128*68
    float* Ks    = Qs + 128 * QK_STR;          // 128*68  (also V: mv rows 0..63, cv rows 64..127)
    float* Ssc   = Ks + 128 * QK_STR;          // 64*516
    float* aqs   = Ssc + 64 * SC_STR;          // 64
    float* aks   = aqs + 64;                   // 512
    float* invzs = aks + 512;                  // 64

    const int tid = threadIdx.x;
    const int q0  = blockIdx.x * 64;
    const int h   = blockIdx.y;
    const int b   = blockIdx.z;
    const int tx  = tid & 15;
    const int ty  = tid >> 4;

    // ---- load Q tile (transposed) + row scalars ----
#pragma unroll
    for (int u = 0; u < 4; u++) {
        int lin = u * 256 + tid;
        int row = lin >> 4;
        int c4  = (lin & 15) << 2;
        int g = ((b * 512 + q0 + row) * 256) + h * 64 + c4;
        float4 vm = *(const float4*)(g_mq + g);
        float4 vs = *(const float4*)(g_sq + g);
        Qs[(c4 + 0) * QK_STR + row] = vm.x; Qs[(c4 + 1) * QK_STR + row] = vm.y;
        Qs[(c4 + 2) * QK_STR + row] = vm.z; Qs[(c4 + 3) * QK_STR + row] = vm.w;
        Qs[(64 + c4 + 0) * QK_STR + row] = vs.x; Qs[(64 + c4 + 1) * QK_STR + row] = vs.y;
        Qs[(64 + c4 + 2) * QK_STR + row] = vs.z; Qs[(64 + c4 + 3) * QK_STR + row] = vs.w;
    }
    if (tid < 64) aqs[tid] = g_aq[(b * 4 + h) * 512 + q0 + tid];
    aks[tid]       = g_ak[(b * 4 + h) * 512 + tid];
    aks[tid + 256] = g_ak[(b * 4 + h) * 512 + 256 + tid];

    const float* mrow = mask + ((size_t)b * 512 + q0) * 512;

    // ---- scores: e = exp(-dist)/8 + mask ----
    for (int kt = 0; kt < 8; kt++) {
        __syncthreads();
        const int k0 = kt * 64;
#pragma unroll
        for (int u = 0; u < 4; u++) {
            int lin = u * 256 + tid;
            int row = lin >> 4;
            int c4  = (lin & 15) << 2;
            int g = ((b * 512 + k0 + row) * 256) + h * 64 + c4;
            float4 vm = *(const float4*)(g_mk + g);
            float4 vs = *(const float4*)(g_sk + g);
            Ks[(c4 + 0) * QK_STR + row] = vm.x; Ks[(c4 + 1) * QK_STR + row] = vm.y;
            Ks[(c4 + 2) * QK_STR + row] = vm.z; Ks[(c4 + 3) * QK_STR + row] = vm.w;
            Ks[(64 + c4 + 0) * QK_STR + row] = vs.x; Ks[(64 + c4 + 1) * QK_STR + row] = vs.y;
            Ks[(64 + c4 + 2) * QK_STR + row] = vs.z; Ks[(64 + c4 + 3) * QK_STR + row] = vs.w;
        }
        __syncthreads();

        float acc[4][4];
#pragma unroll
        for (int r = 0; r < 4; r++)
#pragma unroll
            for (int c = 0; c < 4; c++) acc[r][c] = 0.f;

#pragma unroll 8
        for (int kk = 0; kk < 128; kk++) {
            float4 a  = *(const float4*)&Qs[kk * QK_STR + ty * 4];
            float4 bq = *(const float4*)&Ks[kk * QK_STR + tx * 4];
            float a4[4] = {a.x, a.y, a.z, a.w};
            float b4[4] = {bq.x, bq.y, bq.z, bq.w};
#pragma unroll
            for (int r = 0; r < 4; r++)
#pragma unroll
                for (int c = 0; c < 4; c++)
                    acc[r][c] = fmaf(a4[r], b4[c], acc[r][c]);
        }
#pragma unroll
        for (int r = 0; r < 4; r++) {
            const int i = ty * 4 + r;
            const float aq_i = aqs[i];
#pragma unroll
            for (int c = 0; c < 4; c++) {
                const int j = k0 + tx * 4 + c;
                float dist = aq_i + aks[j] - 2.f * acc[r][c];
                float e = fexp(-dist) * 0.125f + mrow[(size_t)i * 512 + j];
                Ssc[i * SC_STR + j] = e;
            }
        }
    }
    __syncthreads();

    // ---- softmax row stats (4 threads per row) ----
    {
        const int row = tid >> 2, sub = tid & 3;
        float m = -3.0e38f;
        for (int k = sub; k < 512; k += 4) m = fmaxf(m, Ssc[row * SC_STR + k]);
        m = fmaxf(m, __shfl_xor_sync(~0u, m, 1));
        m = fmaxf(m, __shfl_xor_sync(~0u, m, 2));
        float s = 0.f;
        for (int k = sub; k < 512; k += 4) {
            float e = fexp(Ssc[row * SC_STR + k] - m);
            Ssc[row * SC_STR + k] = e;
            s += e;
        }
        s += __shfl_xor_sync(~0u, s, 1);
        s += __shfl_xor_sync(~0u, s, 2);
        if (sub == 0) invzs[row] = 1.f / s;
    }
    __syncthreads();

    // ---- normalize in smem + write probs (coalesced float4) ----
    {
        const size_t pbase = (((size_t)(b * 4 + h)) * 512 + q0) * 512;
#pragma unroll
        for (int u = 0; u < 32; u++) {
            int lin = u * 256 + tid;
            int i   = lin >> 7;
            int k4  = (lin & 127) << 2;
            float z = invzs[i];
            float4 p = *(float4*)&Ssc[i * SC_STR + k4];
            p.x *= z; p.y *= z; p.z *= z; p.w *= z;
            *(float4*)&Ssc[i * SC_STR + k4] = p;
            *(float4*)(probs + pbase + (size_t)i * 512 + k4) = p;
        }
    }
    __syncthreads();

    // ---- PV: ctx_m = P@mv, ctx_c = (P*P)@cv ----
    float am[4][4], ac[4][4];
#pragma unroll
    for (int r = 0; r < 4; r++)
#pragma unroll
        for (int c = 0; c < 4; c++) { am[r][c] = 0.f; ac[r][c] = 0.f; }

    for (int kt = 0; kt < 8; kt++) {
        __syncthreads();
#pragma unroll
        for (int u = 0; u < 4; u++) {
            int lin = u * 256 + tid;
            int row = lin >> 4;
            int c4  = (lin & 15) << 2;
            int g = ((b * 512 + kt * 64 + row) * 256) + h * 64 + c4;
            *(float4*)&Ks[row * QK_STR + c4]        = *(const float4*)(g_mv + g);
            *(float4*)&Ks[(64 + row) * QK_STR + c4] = *(const float4*)(g_cv + g);
        }
        __syncthreads();
#pragma unroll 4
        for (int kk = 0; kk < 64; kk++) {
            float p[4], p2[4];
#pragma unroll
            for (int r = 0; r < 4; r++) {
                p[r]  = Ssc[(ty * 4 + r) * SC_STR + kt * 64 + kk];
                p2[r] = p[r] * p[r];
            }
            float4 vm = *(const float4*)&Ks[kk * QK_STR + tx * 4];
            float4 vc = *(const float4*)&Ks[(64 + kk) * QK_STR + tx * 4];
            float vmv[4] = {vm.x, vm.y, vm.z, vm.w};
            float vcv[4] = {vc.x, vc.y, vc.z, vc.w};
#pragma unroll
            for (int r = 0; r < 4; r++)
#pragma unroll
                for (int c = 0; c < 4; c++) {
                    am[r][c] = fmaf(p[r],  vmv[c], am[r][c]);
                    ac[r][c] = fmaf(p2[r], vcv[c], ac[r][c]);
                }
        }
    }

#pragma unroll
    for (int r = 0; r < 4; r++) {
        int g = ((b * 512 + q0 + ty * 4 + r) * 256) + h * 64 + tx * 4;
        float4 om = make_float4(am[r][0], am[r][1], am[r][2], am[r][3]);
        float4 oc = make_float4(ac[r][0], ac[r][1], ac[r][2], ac[r][3]);
        *(float4*)(g_ctxm + g) = om;
        *(float4*)(g_ctxc + g) = oc;
    }
}

// ---------------------------------------------------------------------------
// LayerNorm: out = lw * norm(D + X) + lb   (row length 256, one block per row)
// ---------------------------------------------------------------------------
__global__ __launch_bounds__(256)
void ln_kernel(const float* __restrict__ D, const float* __restrict__ X,
               const float* __restrict__ lw, const float* __restrict__ lb,
               float* __restrict__ O)
{
    __shared__ float red[16];
    const int r = blockIdx.x, t = threadIdx.x;
    const size_t base = (size_t)r * 256;
    float v = D[base + t] + X[base + t];
    float s1 = v, s2 = v * v;
#pragma unroll
    for (int o = 16; o; o >>= 1) {
        s1 += __shfl_xor_sync(~0u, s1, o);
        s2 += __shfl_xor_sync(~0u, s2, o);
    }
    const int wid = t >> 5, lane = t & 31;
    if (!lane) { red[wid] = s1; red[8 + wid] = s2; }
    __syncthreads();
    float S1 = 0.f, S2 = 0.f;
#pragma unroll
    for (int i = 0; i < 8; i++) { S1 += red[i]; S2 += red[8 + i]; }
    float u   = S1 * (1.f / 256.f);
    float var = fmaxf(S2 * (1.f / 256.f) - u * u, 0.f);
    float y = fmaf(lw[t], (v - u) * rsqrtf(var + 1e-12f), lb[t]);
    O[base + t] = y;
}

// ---------------------------------------------------------------------------
// kernel_launch
// ---------------------------------------------------------------------------
extern "C" void kernel_launch(void* const* d_in, const int* in_sizes, int n_in,
                              void* d_out, int out_size)
{
    (void)in_sizes; (void)n_in; (void)out_size;
    const float* in_mean = (const float*)d_in[0];
    const float* in_cov  = (const float*)d_in[1];
    const float* mask    = (const float*)d_in[2];
    const float* Wmq = (const float*)d_in[3];  const float* bmq = (const float*)d_in[4];
    const float* Wmk = (const float*)d_in[5];  const float* bmk = (const float*)d_in[6];
    const float* Wmv = (const float*)d_in[7];  const float* bmv = (const float*)d_in[8];
    const float* Wcq = (const float*)d_in[9];  const float* bcq = (const float*)d_in[10];
    const float* Wck = (const float*)d_in[11]; const float* bck = (const float*)d_in[12];
    const float* Wcv = (const float*)d_in[13]; const float* bcv = (const float*)d_in[14];
    const float* Wmd = (const float*)d_in[15]; const float* bmd = (const float*)d_in[16];
    const float* Wcd = (const float*)d_in[17]; const float* bcd = (const float*)d_in[18];
    const float* lw  = (const float*)d_in[19]; const float* lb  = (const float*)d_in[20];
    float* out = (float*)d_out;

    float *mq, *mk, *mv, *sq, *sk, *cv, *ctxm, *ctxc, *dm, *dc, *aq, *ak;
    cudaGetSymbolAddress((void**)&mq,   g_mq);
    cudaGetSymbolAddress((void**)&mk,   g_mk);
    cudaGetSymbolAddress((void**)&mv,   g_mv);
    cudaGetSymbolAddress((void**)&sq,   g_sq);
    cudaGetSymbolAddress((void**)&sk,   g_sk);
    cudaGetSymbolAddress((void**)&cv,   g_cv);
    cudaGetSymbolAddress((void**)&ctxm, g_ctxm);
    cudaGetSymbolAddress((void**)&ctxc, g_ctxc);
    cudaGetSymbolAddress((void**)&dm,   g_dm);
    cudaGetSymbolAddress((void**)&dc,   g_dc);
    cudaGetSymbolAddress((void**)&aq,   g_aq);
    cudaGetSymbolAddress((void**)&ak,   g_ak);

    dim3 gg(MROWS / 128, 2);

    // projections
    gemm256<<<gg, 256>>>(in_mean, Wmq, bmq, mq, 0);
    gemm256<<<gg, 256>>>(in_mean, Wmk, bmk, mk, 0);
    gemm256<<<gg, 256>>>(in_mean, Wmv, bmv, mv, 0);
    gemm256<<<gg, 256>>>(in_cov,  Wcq, bcq, sq, 2);
    gemm256<<<gg, 256>>>(in_cov,  Wck, bck, sk, 2);
    gemm256<<<gg, 256>>>(in_cov,  Wcv, bcv, cv, 1);

    // row scalars
    rowsum_kernel<<<NROW / 8, 256>>>(mq, sq, aq);
    rowsum_kernel<<<NROW / 8, 256>>>(mk, sk, ak);

    // attention (+probs output at offset 2*MAT)
    cudaFuncSetAttribute(attn_kernel,
                         cudaFuncAttributeMaxDynamicSharedMemorySize,
                         ATT_SMEM_BYTES);
    attn_kernel<<<dim3(SS / 64, NH, BB), 256, ATT_SMEM_BYTES>>>(mask, out + 2 * (size_t)MAT);

    // output denses
    gemm256<<<gg, 256>>>(ctxm, Wmd, bmd, dm, 0);
    gemm256<<<gg, 256>>>(ctxc, Wcd, bcd, dc, 0);

    // residual + layernorm -> outputs
    ln_kernel<<<MROWS, 256>>>(dm, in_mean, lw, lb, out);
    ln_kernel<<<MROWS, 256>>>(dc, in_cov,  lw, lb, out + (size_t)MAT);
}

// round 4
// speedup vs baseline: 1.2047x; 1.2047x over previous
#include <cuda_runtime.h>
#include <cuda_bf16.h>
#include <stdint.h>
#include <math.h>

// ---------------------------------------------------------------------------
// Problem constants
// ---------------------------------------------------------------------------
#define BB   64
#define SS   512
#define HID  256
#define NH   4
#define DH   64
#define MROWS (BB*SS)            // 32768
#define MAT   (MROWS*HID)        // 8388608
#define NROW  (BB*NH*SS)         // 131072
#define WSZ   (HID*HID)          // 65536

// ---------------------------------------------------------------------------
// Scratch (device globals; no allocation allowed)
// ---------------------------------------------------------------------------
__device__ float g_mq[MAT];
__device__ float g_mk[MAT];
__device__ float g_mv[MAT];
__device__ float g_sq[MAT];
__device__ float g_sk[MAT];
__device__ float g_cv[MAT];
__device__ float g_ctxm[MAT];
__device__ float g_ctxc[MAT];
__device__ float g_dm[MAT];
__device__ float g_dc[MAT];
__device__ float g_aq[NROW];
__device__ float g_ak[NROW];
// bf16 split buffers
__device__ __nv_bfloat16 g_xmh[MAT], g_xml[MAT];   // in_mean hi/lo
__device__ __nv_bfloat16 g_xch[MAT], g_xcl[MAT];   // in_cov  hi/lo
__device__ __nv_bfloat16 g_cmh[MAT], g_cml[MAT];   // ctxm    hi/lo
__device__ __nv_bfloat16 g_cch[MAT], g_ccl[MAT];   // ctxc    hi/lo
__device__ __nv_bfloat16 g_wh[8*WSZ], g_wl[8*WSZ]; // 8 weights hi/lo

// ---------------------------------------------------------------------------
// Helpers
// ---------------------------------------------------------------------------
__device__ __forceinline__ uint32_t smem_u32(const void* p) {
    uint32_t a;
    asm("{ .reg .u64 t; cvta.to.shared.u64 t, %1; cvt.u32.u64 %0, t; }"
        : "=r"(a) : "l"(p));
    return a;
}

#define LDSM_X4(d, addr) \
    asm volatile("ldmatrix.sync.aligned.m8n8.x4.shared.b16 {%0,%1,%2,%3}, [%4];" \
        : "=r"((d)[0]), "=r"((d)[1]), "=r"((d)[2]), "=r"((d)[3]) : "r"(addr))

#define MMA_BF16(c, a, b) \
    asm volatile("mma.sync.aligned.m16n8k16.row.col.f32.bf16.bf16.f32 " \
        "{%0,%1,%2,%3}, {%4,%5,%6,%7}, {%8,%9}, {%0,%1,%2,%3};" \
        : "+f"((c)[0]), "+f"((c)[1]), "+f"((c)[2]), "+f"((c)[3]) \
        : "r"((a)[0]), "r"((a)[1]), "r"((a)[2]), "r"((a)[3]), \
          "r"((b)[0]), "r"((b)[1]))

// Fast exp (FFMA pipe). |rel err| ~3e-6.
__device__ __forceinline__ float fexp(float x) {
    x = fmaxf(fminf(x, 80.f), -87.f);
    float y = x * 1.4426950408889634f;
    int   i = __float2int_rn(y);
    float f = y - (float)i;
    float p = 1.3333558146e-3f;
    p = fmaf(p, f, 9.6181291918e-3f);
    p = fmaf(p, f, 5.5504108664e-2f);
    p = fmaf(p, f, 2.4022650696e-1f);
    p = fmaf(p, f, 6.9314718056e-1f);
    p = fmaf(p, f, 1.0f);
    return __int_as_float(__float_as_int(p) + (i << 23));
}

// ---------------------------------------------------------------------------
// fp32 -> bf16 hi/lo split
// ---------------------------------------------------------------------------
__global__ __launch_bounds__(256)
void split_bf16(const float* __restrict__ x, __nv_bfloat16* __restrict__ hi,
                __nv_bfloat16* __restrict__ lo, int n4)
{
    int i = blockIdx.x * 256 + threadIdx.x;
    if (i >= n4) return;
    float4 v = ((const float4*)x)[i];
    __nv_bfloat16 h0 = __float2bfloat16(v.x);
    __nv_bfloat16 h1 = __float2bfloat16(v.y);
    __nv_bfloat16 h2 = __float2bfloat16(v.z);
    __nv_bfloat16 h3 = __float2bfloat16(v.w);
    __nv_bfloat16 l0 = __float2bfloat16(v.x - __bfloat162float(h0));
    __nv_bfloat16 l1 = __float2bfloat16(v.y - __bfloat162float(h1));
    __nv_bfloat16 l2 = __float2bfloat16(v.z - __bfloat162float(h2));
    __nv_bfloat16 l3 = __float2bfloat16(v.w - __bfloat162float(h3));
    __nv_bfloat162 p0, p1, q0, q1;
    p0.x = h0; p0.y = h1; p1.x = h2; p1.y = h3;
    q0.x = l0; q0.y = l1; q1.x = l2; q1.y = l3;
    ((__nv_bfloat162*)hi)[i * 2]     = p0;
    ((__nv_bfloat162*)hi)[i * 2 + 1] = p1;
    ((__nv_bfloat162*)lo)[i * 2]     = q0;
    ((__nv_bfloat162*)lo)[i * 2 + 1] = q1;
}

// ---------------------------------------------------------------------------
// HMMA GEMM: Y[M=32768,N=256] = X[M,256] @ W[256,256]^T + bias, epilogue.
// bf16x3 split precision, fp32 accumulators (mma.sync m16n8k16).
// CTA = 128x128 tile, 8 warps (2 M x 4 N), warp tile 64x32.
// ep=0: none ; ep=1: elu()+1 ; ep=2: sqrt(max(elu()+1, 1e-24))
// ---------------------------------------------------------------------------
#define SSTR 40   // smem row stride in bf16 (32 data + 8 pad) -> conflict-free ldmatrix

__global__ __launch_bounds__(256)
void gemm_hmma(const __nv_bfloat16* __restrict__ Ah, const __nv_bfloat16* __restrict__ Al,
               const __nv_bfloat16* __restrict__ Bh, const __nv_bfloat16* __restrict__ Bl,
               const float* __restrict__ bias, float* __restrict__ Y, int ep)
{
    __shared__ __align__(16) __nv_bfloat16 sA[2][128 * SSTR];
    __shared__ __align__(16) __nv_bfloat16 sB[2][128 * SSTR];

    const int tid  = threadIdx.x;
    const int wid  = tid >> 5;
    const int lane = tid & 31;
    const int m0   = blockIdx.x * 128;
    const int n0   = blockIdx.y * 128;
    const int wm   = (wid & 1) * 64;    // warp M offset in tile
    const int wn   = (wid >> 1) * 32;   // warp N offset in tile

    float c[4][4][4];
#pragma unroll
    for (int mi = 0; mi < 4; mi++)
#pragma unroll
        for (int ni = 0; ni < 4; ni++)
#pragma unroll
            for (int e = 0; e < 4; e++) c[mi][ni][e] = 0.f;

    for (int kc = 0; kc < 8; kc++) {       // K chunks of 32
        __syncthreads();
#pragma unroll
        for (int u = 0; u < 2; u++) {
            int idx = u * 256 + tid;       // 0..511
            int row = idx >> 2;            // 0..127
            int f4  = idx & 3;             // 0..3 (8 bf16 each)
            int soff = row * SSTR + f4 * 8;
            const size_t ga = (size_t)(m0 + row) * 256 + kc * 32 + f4 * 8;
            const size_t gb = (size_t)(n0 + row) * 256 + kc * 32 + f4 * 8;
            *(float4*)&sA[0][soff] = *(const float4*)(Ah + ga);
            *(float4*)&sA[1][soff] = *(const float4*)(Al + ga);
            *(float4*)&sB[0][soff] = *(const float4*)(Bh + gb);
            *(float4*)&sB[1][soff] = *(const float4*)(Bl + gb);
        }
        __syncthreads();

#pragma unroll
        for (int ks = 0; ks < 2; ks++) {   // two k16 steps
            const int kb = ks * 16;
            // A fragments (4 m-groups x 16 rows), hi+lo
            uint32_t ah[4][4], al[4][4];
            {
                const int r  = wm + (lane & 15);
                const int kk = kb + (lane >> 4) * 8;
#pragma unroll
                for (int mi = 0; mi < 4; mi++) {
                    uint32_t aH = smem_u32(&sA[0][(r + mi * 16) * SSTR + kk]);
                    uint32_t aL = smem_u32(&sA[1][(r + mi * 16) * SSTR + kk]);
                    LDSM_X4(ah[mi], aH);
                    LDSM_X4(al[mi], aL);
                }
            }
            // B fragments (4 n-groups of 8), loaded as 2 x ldmatrix.x4, hi+lo
            uint32_t bh[2][4], bl[2][4];
            {
                const int nr = (lane & 7) + ((lane >> 4) & 1) * 8;
                const int kk = kb + ((lane >> 3) & 1) * 8;
#pragma unroll
                for (int ng = 0; ng < 2; ng++) {
                    uint32_t bH = smem_u32(&sB[0][(wn + ng * 16 + nr) * SSTR + kk]);
                    uint32_t bL = smem_u32(&sB[1][(wn + ng * 16 + nr) * SSTR + kk]);
                    LDSM_X4(bh[ng], bH);
                    LDSM_X4(bl[ng], bL);
                }
            }
#pragma unroll
            for (int mi = 0; mi < 4; mi++)
#pragma unroll
                for (int ni = 0; ni < 4; ni++) {
                    uint32_t* bH = &bh[ni >> 1][(ni & 1) * 2];
                    uint32_t* bL = &bl[ni >> 1][(ni & 1) * 2];
                    MMA_BF16(c[mi][ni], ah[mi], bH);
                    MMA_BF16(c[mi][ni], ah[mi], bL);
                    MMA_BF16(c[mi][ni], al[mi], bH);
                }
        }
    }

    // ---- epilogue ----
    const int mrow = m0 + wm + (lane >> 2);
    const int ncol = n0 + wn + 2 * (lane & 3);
#pragma unroll
    for (int mi = 0; mi < 4; mi++) {
#pragma unroll
        for (int ni = 0; ni < 4; ni++) {
            const int col = ncol + ni * 8;
            float v[4];
#pragma unroll
            for (int e = 0; e < 4; e++) {
                float t = c[mi][ni][e] + bias[col - n0 + n0 + (e & 1)];
                if (ep >= 1) t = (t > 0.f) ? (t + 1.f) : __expf(t);
                if (ep == 2) t = sqrtf(fmaxf(t, 1e-24f));
                v[e] = t;
            }
            float* r0 = Y + (size_t)(mrow + mi * 16) * 256 + col;
            float* r1 = Y + (size_t)(mrow + mi * 16 + 8) * 256 + col;
            *(float2*)r0 = make_float2(v[0], v[1]);
            *(float2*)r1 = make_float2(v[2], v[3]);
        }
    }
}

// ---------------------------------------------------------------------------
// Row scalars:  A[(b*4+h)*512+s] = sum_d  M^2 + Sq^2
// ---------------------------------------------------------------------------
__global__ __launch_bounds__(256)
void rowsum_kernel(const float* __restrict__ M, const float* __restrict__ Sq,
                   float* __restrict__ A)
{
    const int w    = (blockIdx.x * blockDim.x + threadIdx.x) >> 5;
    const int lane = threadIdx.x & 31;
    const int s  = w & 511;
    const int bh = w >> 9;
    const int b  = bh >> 2, h = bh & 3;
    const int base = ((b * 512 + s) * 256) + h * 64;
    float vm0 = M[base + lane],  vm1 = M[base + 32 + lane];
    float vs0 = Sq[base + lane], vs1 = Sq[base + 32 + lane];
    float sum = vm0 * vm0 + vm1 * vm1 + vs0 * vs0 + vs1 * vs1;
#pragma unroll
    for (int o = 16; o; o >>= 1) sum += __shfl_xor_sync(~0u, sum, o);
    if (!lane) A[w] = sum;
}

// ---------------------------------------------------------------------------
// Attention (unchanged from R1, known correct)
// ---------------------------------------------------------------------------
#define QK_STR 68
#define SC_STR 516
#define ATT_SMEM_FLOATS (128*QK_STR*2 + 64*SC_STR + 64 + 512 + 64)
#define ATT_SMEM_BYTES  (ATT_SMEM_FLOATS * 4)

__global__ __launch_bounds__(256)
void attn_kernel(const float* __restrict__ mask, float* __restrict__ probs)
{
    extern __shared__ __align__(16) float sm[];
    float* Qs    = sm;
    float* Ks    = Qs + 128 * QK_STR;
    float* Ssc   = Ks + 128 * QK_STR;
    float* aqs   = Ssc + 64 * SC_STR;
    float* aks   = aqs + 64;
    float* invzs = aks + 512;

    const int tid = threadIdx.x;
    const int q0  = blockIdx.x * 64;
    const int h   = blockIdx.y;
    const int b   = blockIdx.z;
    const int tx  = tid & 15;
    const int ty  = tid >> 4;

#pragma unroll
    for (int u = 0; u < 4; u++) {
        int lin = u * 256 + tid;
        int row = lin >> 4;
        int c4  = (lin & 15) << 2;
        int g = ((b * 512 + q0 + row) * 256) + h * 64 + c4;
        float4 vm = *(const float4*)(g_mq + g);
        float4 vs = *(const float4*)(g_sq + g);
        Qs[(c4 + 0) * QK_STR + row] = vm.x; Qs[(c4 + 1) * QK_STR + row] = vm.y;
        Qs[(c4 + 2) * QK_STR + row] = vm.z; Qs[(c4 + 3) * QK_STR + row] = vm.w;
        Qs[(64 + c4 + 0) * QK_STR + row] = vs.x; Qs[(64 + c4 + 1) * QK_STR + row] = vs.y;
        Qs[(64 + c4 + 2) * QK_STR + row] = vs.z; Qs[(64 + c4 + 3) * QK_STR + row] = vs.w;
    }
    if (tid < 64) aqs[tid] = g_aq[(b * 4 + h) * 512 + q0 + tid];
    aks[tid]       = g_ak[(b * 4 + h) * 512 + tid];
    aks[tid + 256] = g_ak[(b * 4 + h) * 512 + 256 + tid];

    const float* mrow = mask + ((size_t)b * 512 + q0) * 512;

    for (int kt = 0; kt < 8; kt++) {
        __syncthreads();
        const int k0 = kt * 64;
#pragma unroll
        for (int u = 0; u < 4; u++) {
            int lin = u * 256 + tid;
            int row = lin >> 4;
            int c4  = (lin & 15) << 2;
            int g = ((b * 512 + k0 + row) * 256) + h * 64 + c4;
            float4 vm = *(const float4*)(g_mk + g);
            float4 vs = *(const float4*)(g_sk + g);
            Ks[(c4 + 0) * QK_STR + row] = vm.x; Ks[(c4 + 1) * QK_STR + row] = vm.y;
            Ks[(c4 + 2) * QK_STR + row] = vm.z; Ks[(c4 + 3) * QK_STR + row] = vm.w;
            Ks[(64 + c4 + 0) * QK_STR + row] = vs.x; Ks[(64 + c4 + 1) * QK_STR + row] = vs.y;
            Ks[(64 + c4 + 2) * QK_STR + row] = vs.z; Ks[(64 + c4 + 3) * QK_STR + row] = vs.w;
        }
        __syncthreads();

        float acc[4][4];
#pragma unroll
        for (int r = 0; r < 4; r++)
#pragma unroll
            for (int c = 0; c < 4; c++) acc[r][c] = 0.f;

#pragma unroll 8
        for (int kk = 0; kk < 128; kk++) {
            float4 a  = *(const float4*)&Qs[kk * QK_STR + ty * 4];
            float4 bq = *(const float4*)&Ks[kk * QK_STR + tx * 4];
            float a4[4] = {a.x, a.y, a.z, a.w};
            float b4[4] = {bq.x, bq.y, bq.z, bq.w};
#pragma unroll
            for (int r = 0; r < 4; r++)
#pragma unroll
                for (int c = 0; c < 4; c++)
                    acc[r][c] = fmaf(a4[r], b4[c], acc[r][c]);
        }
#pragma unroll
        for (int r = 0; r < 4; r++) {
            const int i = ty * 4 + r;
            const float aq_i = aqs[i];
#pragma unroll
            for (int c = 0; c < 4; c++) {
                const int j = k0 + tx * 4 + c;
                float dist = aq_i + aks[j] - 2.f * acc[r][c];
                float e = fexp(-dist) * 0.125f + mrow[(size_t)i * 512 + j];
                Ssc[i * SC_STR + j] = e;
            }
        }
    }
    __syncthreads();

    {
        const int row = tid >> 2, sub = tid & 3;
        float m = -3.0e38f;
        for (int k = sub; k < 512; k += 4) m = fmaxf(m, Ssc[row * SC_STR + k]);
        m = fmaxf(m, __shfl_xor_sync(~0u, m, 1));
        m = fmaxf(m, __shfl_xor_sync(~0u, m, 2));
        float s = 0.f;
        for (int k = sub; k < 512; k += 4) {
            float e = fexp(Ssc[row * SC_STR + k] - m);
            Ssc[row * SC_STR + k] = e;
            s += e;
        }
        s += __shfl_xor_sync(~0u, s, 1);
        s += __shfl_xor_sync(~0u, s, 2);
        if (sub == 0) invzs[row] = 1.f / s;
    }
    __syncthreads();

    {
        const size_t pbase = (((size_t)(b * 4 + h)) * 512 + q0) * 512;
#pragma unroll
        for (int u = 0; u < 32; u++) {
            int lin = u * 256 + tid;
            int i   = lin >> 7;
            int k4  = (lin & 127) << 2;
            float z = invzs[i];
            float4 p = *(float4*)&Ssc[i * SC_STR + k4];
            p.x *= z; p.y *= z; p.z *= z; p.w *= z;
            *(float4*)&Ssc[i * SC_STR + k4] = p;
            *(float4*)(probs + pbase + (size_t)i * 512 + k4) = p;
        }
    }
    __syncthreads();

    float am[4][4], ac[4][4];
#pragma unroll
    for (int r = 0; r < 4; r++)
#pragma unroll
        for (int c = 0; c < 4; c++) { am[r][c] = 0.f; ac[r][c] = 0.f; }

    for (int kt = 0; kt < 8; kt++) {
        __syncthreads();
#pragma unroll
        for (int u = 0; u < 4; u++) {
            int lin = u * 256 + tid;
            int row = lin >> 4;
            int c4  = (lin & 15) << 2;
            int g = ((b * 512 + kt * 64 + row) * 256) + h * 64 + c4;
            *(float4*)&Ks[row * QK_STR + c4]        = *(const float4*)(g_mv + g);
            *(float4*)&Ks[(64 + row) * QK_STR + c4] = *(const float4*)(g_cv + g);
        }
        __syncthreads();
#pragma unroll 4
        for (int kk = 0; kk < 64; kk++) {
            float p[4], p2[4];
#pragma unroll
            for (int r = 0; r < 4; r++) {
                p[r]  = Ssc[(ty * 4 + r) * SC_STR + kt * 64 + kk];
                p2[r] = p[r] * p[r];
            }
            float4 vm = *(const float4*)&Ks[kk * QK_STR + tx * 4];
            float4 vc = *(const float4*)&Ks[(64 + kk) * QK_STR + tx * 4];
            float vmv[4] = {vm.x, vm.y, vm.z, vm.w};
            float vcv[4] = {vc.x, vc.y, vc.z, vc.w};
#pragma unroll
            for (int r = 0; r < 4; r++)
#pragma unroll
                for (int c = 0; c < 4; c++) {
                    am[r][c] = fmaf(p[r],  vmv[c], am[r][c]);
                    ac[r][c] = fmaf(p2[r], vcv[c], ac[r][c]);
                }
        }
    }

#pragma unroll
    for (int r = 0; r < 4; r++) {
        int g = ((b * 512 + q0 + ty * 4 + r) * 256) + h * 64 + tx * 4;
        *(float4*)(g_ctxm + g) = make_float4(am[r][0], am[r][1], am[r][2], am[r][3]);
        *(float4*)(g_ctxc + g) = make_float4(ac[r][0], ac[r][1], ac[r][2], ac[r][3]);
    }
}

// ---------------------------------------------------------------------------
// LayerNorm: out = lw * norm(D + X) + lb
// ---------------------------------------------------------------------------
__global__ __launch_bounds__(256)
void ln_kernel(const float* __restrict__ D, const float* __restrict__ X,
               const float* __restrict__ lw, const float* __restrict__ lb,
               float* __restrict__ O)
{
    __shared__ float red[16];
    const int r = blockIdx.x, t = threadIdx.x;
    const size_t base = (size_t)r * 256;
    float v = D[base + t] + X[base + t];
    float s1 = v, s2 = v * v;
#pragma unroll
    for (int o = 16; o; o >>= 1) {
        s1 += __shfl_xor_sync(~0u, s1, o);
        s2 += __shfl_xor_sync(~0u, s2, o);
    }
    const int wid = t >> 5, lane = t & 31;
    if (!lane) { red[wid] = s1; red[8 + wid] = s2; }
    __syncthreads();
    float S1 = 0.f, S2 = 0.f;
#pragma unroll
    for (int i = 0; i < 8; i++) { S1 += red[i]; S2 += red[8 + i]; }
    float u   = S1 * (1.f / 256.f);
    float var = fmaxf(S2 * (1.f / 256.f) - u * u, 0.f);
    float y = fmaf(lw[t], (v - u) * rsqrtf(var + 1e-12f), lb[t]);
    O[base + t] = y;
}

// ---------------------------------------------------------------------------
// kernel_launch
// ---------------------------------------------------------------------------
extern "C" void kernel_launch(void* const* d_in, const int* in_sizes, int n_in,
                              void* d_out, int out_size)
{
    (void)in_sizes; (void)n_in; (void)out_size;
    const float* in_mean = (const float*)d_in[0];
    const float* in_cov  = (const float*)d_in[1];
    const float* mask    = (const float*)d_in[2];
    const float* W[8]    = { (const float*)d_in[3],  (const float*)d_in[5],
                             (const float*)d_in[7],  (const float*)d_in[9],
                             (const float*)d_in[11], (const float*)d_in[13],
                             (const float*)d_in[15], (const float*)d_in[17] };
    const float* bia[8]  = { (const float*)d_in[4],  (const float*)d_in[6],
                             (const float*)d_in[8],  (const float*)d_in[10],
                             (const float*)d_in[12], (const float*)d_in[14],
                             (const float*)d_in[16], (const float*)d_in[18] };
    const float* lw  = (const float*)d_in[19];
    const float* lb  = (const float*)d_in[20];
    float* out = (float*)d_out;

    float *mq, *mk, *mv, *sq, *sk, *cv, *ctxm, *ctxc, *dm, *dc, *aq, *ak;
    cudaGetSymbolAddress((void**)&mq,   g_mq);
    cudaGetSymbolAddress((void**)&mk,   g_mk);
    cudaGetSymbolAddress((void**)&mv,   g_mv);
    cudaGetSymbolAddress((void**)&sq,   g_sq);
    cudaGetSymbolAddress((void**)&sk,   g_sk);
    cudaGetSymbolAddress((void**)&cv,   g_cv);
    cudaGetSymbolAddress((void**)&ctxm, g_ctxm);
    cudaGetSymbolAddress((void**)&ctxc, g_ctxc);
    cudaGetSymbolAddress((void**)&dm,   g_dm);
    cudaGetSymbolAddress((void**)&dc,   g_dc);
    cudaGetSymbolAddress((void**)&aq,   g_aq);
    cudaGetSymbolAddress((void**)&ak,   g_ak);

    __nv_bfloat16 *xmh, *xml, *xch, *xcl, *cmh, *cml, *cch, *ccl, *wh, *wl;
    cudaGetSymbolAddress((void**)&xmh, g_xmh);
    cudaGetSymbolAddress((void**)&xml, g_xml);
    cudaGetSymbolAddress((void**)&xch, g_xch);
    cudaGetSymbolAddress((void**)&xcl, g_xcl);
    cudaGetSymbolAddress((void**)&cmh, g_cmh);
    cudaGetSymbolAddress((void**)&cml, g_cml);
    cudaGetSymbolAddress((void**)&cch, g_cch);
    cudaGetSymbolAddress((void**)&ccl, g_ccl);
    cudaGetSymbolAddress((void**)&wh,  g_wh);
    cudaGetSymbolAddress((void**)&wl,  g_wl);

    cudaFuncSetAttribute(attn_kernel, cudaFuncAttributeMaxDynamicSharedMemorySize,
                         ATT_SMEM_BYTES);

    // ---- bf16 hi/lo conversions ----
    split_bf16<<<MAT / 4 / 256, 256>>>(in_mean, xmh, xml, MAT / 4);
    split_bf16<<<MAT / 4 / 256, 256>>>(in_cov,  xch, xcl, MAT / 4);
    for (int i = 0; i < 8; i++)
        split_bf16<<<WSZ / 4 / 256, 256>>>(W[i], wh + (size_t)i * WSZ,
                                           wl + (size_t)i * WSZ, WSZ / 4);

    dim3 gg(MROWS / 128, 2);

    // ---- projections (HMMA) ----
    gemm_hmma<<<gg, 256>>>(xmh, xml, wh + 0*WSZ, wl + 0*WSZ, bia[0], mq, 0);
    gemm_hmma<<<gg, 256>>>(xmh, xml, wh + 1*WSZ, wl + 1*WSZ, bia[1], mk, 0);
    gemm_hmma<<<gg, 256>>>(xmh, xml, wh + 2*WSZ, wl + 2*WSZ, bia[2], mv, 0);
    gemm_hmma<<<gg, 256>>>(xch, xcl, wh + 3*WSZ, wl + 3*WSZ, bia[3], sq, 2);
    gemm_hmma<<<gg, 256>>>(xch, xcl, wh + 4*WSZ, wl + 4*WSZ, bia[4], sk, 2);
    gemm_hmma<<<gg, 256>>>(xch, xcl, wh + 5*WSZ, wl + 5*WSZ, bia[5], cv, 1);

    // ---- row scalars ----
    rowsum_kernel<<<NROW / 8, 256>>>(mq, sq, aq);
    rowsum_kernel<<<NROW / 8, 256>>>(mk, sk, ak);

    // ---- attention (probs -> out offset 2*MAT) ----
    attn_kernel<<<dim3(SS / 64, NH, BB), 256, ATT_SMEM_BYTES>>>(mask, out + 2 * (size_t)MAT);

    // ---- output denses (HMMA) ----
    split_bf16<<<MAT / 4 / 256, 256>>>(ctxm, cmh, cml, MAT / 4);
    split_bf16<<<MAT / 4 / 256, 256>>>(ctxc, cch, ccl, MAT / 4);
    gemm_hmma<<<gg, 256>>>(cmh, cml, wh + 6*WSZ, wl + 6*WSZ, bia[6], dm, 0);
    gemm_hmma<<<gg, 256>>>(cch, ccl, wh + 7*WSZ, wl + 7*WSZ, bia[7], dc, 0);

    // ---- residual + layernorm ----
    ln_kernel<<<MROWS, 256>>>(dm, in_mean, lw, lb, out);
    ln_kernel<<<MROWS, 256>>>(dc, in_cov,  lw, lb, out + (size_t)MAT);
}

// round 5
// speedup vs baseline: 1.8632x; 1.5467x over previous
#include <cuda_runtime.h>
#include <cuda_bf16.h>
#include <stdint.h>
#include <math.h>

// ---------------------------------------------------------------------------
// Problem constants
// ---------------------------------------------------------------------------
#define BB   64
#define SS   512
#define HID  256
#define NH   4
#define DH   64
#define MROWS (BB*SS)            // 32768
#define MAT   (MROWS*HID)        // 8388608
#define NROW  (BB*NH*SS)         // 131072
#define WSZ   (HID*HID)          // 65536

// ---------------------------------------------------------------------------
// Scratch (device globals; no allocation allowed)
// ---------------------------------------------------------------------------
__device__ float g_mq[MAT];
__device__ float g_mk[MAT];
__device__ float g_mv[MAT];
__device__ float g_sq[MAT];
__device__ float g_sk[MAT];
__device__ float g_cv[MAT];
__device__ float g_dm[MAT];
__device__ float g_dc[MAT];
__device__ float g_aq[NROW];
__device__ float g_ak[NROW];
// bf16 split buffers
__device__ __nv_bfloat16 g_xmh[MAT], g_xml[MAT];   // in_mean hi/lo
__device__ __nv_bfloat16 g_xch[MAT], g_xcl[MAT];   // in_cov  hi/lo
__device__ __nv_bfloat16 g_cmh[MAT], g_cml[MAT];   // ctx_m   hi/lo (written by attn)
__device__ __nv_bfloat16 g_cch[MAT], g_ccl[MAT];   // ctx_c   hi/lo (written by attn)
__device__ __nv_bfloat16 g_wh[8*WSZ], g_wl[8*WSZ]; // 8 weights hi/lo

// ---------------------------------------------------------------------------
// Helpers
// ---------------------------------------------------------------------------
__device__ __forceinline__ uint32_t smem_u32(const void* p) {
    uint32_t a;
    asm("{ .reg .u64 t; cvta.to.shared.u64 t, %1; cvt.u32.u64 %0, t; }"
        : "=r"(a) : "l"(p));
    return a;
}

#define LDSM_X4(d, addr) \
    asm volatile("ldmatrix.sync.aligned.m8n8.x4.shared.b16 {%0,%1,%2,%3}, [%4];" \
        : "=r"((d)[0]), "=r"((d)[1]), "=r"((d)[2]), "=r"((d)[3]) : "r"(addr))

#define LDSM_X4_T(d, addr) \
    asm volatile("ldmatrix.sync.aligned.m8n8.x4.trans.shared.b16 {%0,%1,%2,%3}, [%4];" \
        : "=r"((d)[0]), "=r"((d)[1]), "=r"((d)[2]), "=r"((d)[3]) : "r"(addr))

#define MMA_BF16(c, a, b) \
    asm volatile("mma.sync.aligned.m16n8k16.row.col.f32.bf16.bf16.f32 " \
        "{%0,%1,%2,%3}, {%4,%5,%6,%7}, {%8,%9}, {%0,%1,%2,%3};" \
        : "+f"((c)[0]), "+f"((c)[1]), "+f"((c)[2]), "+f"((c)[3]) \
        : "r"((a)[0]), "r"((a)[1]), "r"((a)[2]), "r"((a)[3]), \
          "r"((b)[0]), "r"((b)[1]))

// pack 2 floats -> bf16x2 (hi), and residual (lo)
__device__ __forceinline__ uint32_t packh(float x, float y) {
    __nv_bfloat162 r; r.x = __float2bfloat16(x); r.y = __float2bfloat16(y);
    return *(uint32_t*)&r;
}
__device__ __forceinline__ uint32_t packl(float x, float y, uint32_t hp) {
    __nv_bfloat162 h = *(__nv_bfloat162*)&hp;
    __nv_bfloat162 r;
    r.x = __float2bfloat16(x - __bfloat162float(h.x));
    r.y = __float2bfloat16(y - __bfloat162float(h.y));
    return *(uint32_t*)&r;
}

// Fast exp (FFMA pipe). |rel err| ~3e-6.
__device__ __forceinline__ float fexp(float x) {
    x = fmaxf(fminf(x, 80.f), -87.f);
    float y = x * 1.4426950408889634f;
    int   i = __float2int_rn(y);
    float f = y - (float)i;
    float p = 1.3333558146e-3f;
    p = fmaf(p, f, 9.6181291918e-3f);
    p = fmaf(p, f, 5.5504108664e-2f);
    p = fmaf(p, f, 2.4022650696e-1f);
    p = fmaf(p, f, 6.9314718056e-1f);
    p = fmaf(p, f, 1.0f);
    return __int_as_float(__float_as_int(p) + (i << 23));
}

// ---------------------------------------------------------------------------
// fp32 -> bf16 hi/lo split
// ---------------------------------------------------------------------------
__global__ __launch_bounds__(256)
void split_bf16(const float* __restrict__ x, __nv_bfloat16* __restrict__ hi,
                __nv_bfloat16* __restrict__ lo, int n4)
{
    int i = blockIdx.x * 256 + threadIdx.x;
    if (i >= n4) return;
    float4 v = ((const float4*)x)[i];
    uint32_t h0 = packh(v.x, v.y), h1 = packh(v.z, v.w);
    uint32_t l0 = packl(v.x, v.y, h0), l1 = packl(v.z, v.w, h1);
    ((uint32_t*)hi)[i * 2]     = h0;
    ((uint32_t*)hi)[i * 2 + 1] = h1;
    ((uint32_t*)lo)[i * 2]     = l0;
    ((uint32_t*)lo)[i * 2 + 1] = l1;
}

// ---------------------------------------------------------------------------
// HMMA GEMM (unchanged from R4, proven): Y = X @ W^T + bias, epilogue
// ---------------------------------------------------------------------------
#define SSTR 40

__global__ __launch_bounds__(256)
void gemm_hmma(const __nv_bfloat16* __restrict__ Ah, const __nv_bfloat16* __restrict__ Al,
               const __nv_bfloat16* __restrict__ Bh, const __nv_bfloat16* __restrict__ Bl,
               const float* __restrict__ bias, float* __restrict__ Y, int ep)
{
    __shared__ __align__(16) __nv_bfloat16 sA[2][128 * SSTR];
    __shared__ __align__(16) __nv_bfloat16 sB[2][128 * SSTR];

    const int tid  = threadIdx.x;
    const int wid  = tid >> 5;
    const int lane = tid & 31;
    const int m0   = blockIdx.x * 128;
    const int n0   = blockIdx.y * 128;
    const int wm   = (wid & 1) * 64;
    const int wn   = (wid >> 1) * 32;

    float c[4][4][4];
#pragma unroll
    for (int mi = 0; mi < 4; mi++)
#pragma unroll
        for (int ni = 0; ni < 4; ni++)
#pragma unroll
            for (int e = 0; e < 4; e++) c[mi][ni][e] = 0.f;

    for (int kc = 0; kc < 8; kc++) {
        __syncthreads();
#pragma unroll
        for (int u = 0; u < 2; u++) {
            int idx = u * 256 + tid;
            int row = idx >> 2;
            int f4  = idx & 3;
            int soff = row * SSTR + f4 * 8;
            const size_t ga = (size_t)(m0 + row) * 256 + kc * 32 + f4 * 8;
            const size_t gb = (size_t)(n0 + row) * 256 + kc * 32 + f4 * 8;
            *(float4*)&sA[0][soff] = *(const float4*)(Ah + ga);
            *(float4*)&sA[1][soff] = *(const float4*)(Al + ga);
            *(float4*)&sB[0][soff] = *(const float4*)(Bh + gb);
            *(float4*)&sB[1][soff] = *(const float4*)(Bl + gb);
        }
        __syncthreads();

#pragma unroll
        for (int ks = 0; ks < 2; ks++) {
            const int kb = ks * 16;
            uint32_t ah[4][4], al[4][4];
            {
                const int r  = wm + (lane & 15);
                const int kk = kb + (lane >> 4) * 8;
#pragma unroll
                for (int mi = 0; mi < 4; mi++) {
                    LDSM_X4(ah[mi], smem_u32(&sA[0][(r + mi * 16) * SSTR + kk]));
                    LDSM_X4(al[mi], smem_u32(&sA[1][(r + mi * 16) * SSTR + kk]));
                }
            }
            uint32_t bh[2][4], bl[2][4];
            {
                const int nr = (lane & 7) + ((lane >> 4) & 1) * 8;
                const int kk = kb + ((lane >> 3) & 1) * 8;
#pragma unroll
                for (int ng = 0; ng < 2; ng++) {
                    LDSM_X4(bh[ng], smem_u32(&sB[0][(wn + ng * 16 + nr) * SSTR + kk]));
                    LDSM_X4(bl[ng], smem_u32(&sB[1][(wn + ng * 16 + nr) * SSTR + kk]));
                }
            }
#pragma unroll
            for (int mi = 0; mi < 4; mi++)
#pragma unroll
                for (int ni = 0; ni < 4; ni++) {
                    uint32_t* bH = &bh[ni >> 1][(ni & 1) * 2];
                    uint32_t* bL = &bl[ni >> 1][(ni & 1) * 2];
                    MMA_BF16(c[mi][ni], ah[mi], bH);
                    MMA_BF16(c[mi][ni], ah[mi], bL);
                    MMA_BF16(c[mi][ni], al[mi], bH);
                }
        }
    }

    const int mrow = m0 + wm + (lane >> 2);
    const int ncol = n0 + wn + 2 * (lane & 3);
#pragma unroll
    for (int mi = 0; mi < 4; mi++) {
#pragma unroll
        for (int ni = 0; ni < 4; ni++) {
            const int col = ncol + ni * 8;
            float v[4];
#pragma unroll
            for (int e = 0; e < 4; e++) {
                float t = c[mi][ni][e] + bias[col - n0 + (e & 1)];
                if (ep >= 1) t = (t > 0.f) ? (t + 1.f) : __expf(t);
                if (ep == 2) t = sqrtf(fmaxf(t, 1e-24f));
                v[e] = t;
            }
            float* r0 = Y + (size_t)(mrow + mi * 16) * 256 + col;
            float* r1 = Y + (size_t)(mrow + mi * 16 + 8) * 256 + col;
            *(float2*)r0 = make_float2(v[0], v[1]);
            *(float2*)r1 = make_float2(v[2], v[3]);
        }
    }
}

// ---------------------------------------------------------------------------
// Row scalars:  A[(b*4+h)*512+s] = sum_d  M^2 + Sq^2
// ---------------------------------------------------------------------------
__global__ __launch_bounds__(256)
void rowsum_kernel(const float* __restrict__ M, const float* __restrict__ Sq,
                   float* __restrict__ A)
{
    const int w    = (blockIdx.x * blockDim.x + threadIdx.x) >> 5;
    const int lane = threadIdx.x & 31;
    const int s  = w & 511;
    const int bh = w >> 9;
    const int b  = bh >> 2, h = bh & 3;
    const int base = ((b * 512 + s) * 256) + h * 64;
    float vm0 = M[base + lane],  vm1 = M[base + 32 + lane];
    float vs0 = Sq[base + lane], vs1 = Sq[base + 32 + lane];
    float sum = vm0 * vm0 + vm1 * vm1 + vs0 * vs0 + vs1 * vs1;
#pragma unroll
    for (int o = 16; o; o >>= 1) sum += __shfl_xor_sync(~0u, sum, o);
    if (!lane) A[w] = sum;
}

// ---------------------------------------------------------------------------
// Tensor-core attention: one CTA = (b, h, 64-query tile), 256 threads/8 warps.
// Phase A: S = Qc@Kc^T via bf16x3 HMMA -> e = exp(-dist)/8 + mask into Ssc.
// Phase B: softmax (2-pass, stable), write probs, leave P in Ssc.
// Phase C: ctx_m = P@mv, ctx_c = P^2@cv via bf16x3 HMMA (A-frags built from
//          fp32 P in smem; V-frags via ldmatrix.trans). Writes bf16 hi/lo ctx.
// ---------------------------------------------------------------------------
#define SC_STR 516
#define QS 136          // Q/K smem stride in bf16 (128 + 8 pad)
#define VS 72           // V smem stride in bf16 (64 + 8 pad)
#define ATT_SMEM_FLOATS (640 + 64*SC_STR + 17408)
#define ATT_SMEM_BYTES  (ATT_SMEM_FLOATS * 4)   // 204288

__global__ __launch_bounds__(256)
void attn_tc(const float* __restrict__ mask, float* __restrict__ probs)
{
    extern __shared__ __align__(16) float sm[];
    float* aqs   = sm;               // 64
    float* aks   = sm + 64;          // 512
    float* invzs = sm + 576;         // 64
    float* Ssc   = sm + 640;         // 64 x 516
    __nv_bfloat16* Qhi = (__nv_bfloat16*)(sm + 640 + 64 * SC_STR);
    __nv_bfloat16* Qlo = Qhi + 64 * QS;          // 8704 bf16 each
    __nv_bfloat16* Khi = Qhi + 2 * 64 * QS;
    __nv_bfloat16* Klo = Qhi + 3 * 64 * QS;
    // phase C aliases the Q/K region
    __nv_bfloat16* Vmh = Qhi;
    __nv_bfloat16* Vml = Qhi + 64 * VS;
    __nv_bfloat16* Vch = Qhi + 2 * 64 * VS;
    __nv_bfloat16* Vcl = Qhi + 3 * 64 * VS;

    const int tid  = threadIdx.x;
    const int wid  = tid >> 5;
    const int lane = tid & 31;
    const int g    = lane >> 2;
    const int t    = lane & 3;
    const int q0   = blockIdx.x * 64;
    const int h    = blockIdx.y;
    const int b    = blockIdx.z;
    const int wm2  = (wid & 1) * 32;     // warp q-offset
    const int wn   = (wid >> 1) * 16;    // warp key-offset (phase A) / d-offset (phase C)

    // scalars
    if (tid < 64) aqs[tid] = g_aq[(b * 4 + h) * 512 + q0 + tid];
    aks[tid]       = g_ak[(b * 4 + h) * 512 + tid];
    aks[tid + 256] = g_ak[(b * 4 + h) * 512 + 256 + tid];

    // ---- load Q (64 x 128 feats = [mq | sq]) as bf16 hi/lo ----
#pragma unroll
    for (int u = 0; u < 8; u++) {
        int idx = u * 256 + tid;           // 0..2047
        int row = idx >> 5;                // 0..63
        int f4  = (idx & 31) * 4;          // 0..124
        const float* src = (f4 < 64)
            ? (g_mq + ((b * 512 + q0 + row) * 256) + h * 64 + f4)
            : (g_sq + ((b * 512 + q0 + row) * 256) + h * 64 + (f4 - 64));
        float4 v = *(const float4*)src;
        uint32_t h0 = packh(v.x, v.y), h1 = packh(v.z, v.w);
        uint32_t l0 = packl(v.x, v.y, h0), l1 = packl(v.z, v.w, h1);
        *(uint2*)&Qhi[row * QS + f4] = make_uint2(h0, h1);
        *(uint2*)&Qlo[row * QS + f4] = make_uint2(l0, l1);
    }

    const float* mrow = mask + ((size_t)b * 512 + q0) * 512;

    // ================= Phase A: scores =================
    for (int kt = 0; kt < 8; kt++) {
        __syncthreads();
#pragma unroll
        for (int u = 0; u < 8; u++) {
            int idx = u * 256 + tid;
            int row = idx >> 5;            // key 0..63
            int f4  = (idx & 31) * 4;
            const float* src = (f4 < 64)
                ? (g_mk + ((b * 512 + kt * 64 + row) * 256) + h * 64 + f4)
                : (g_sk + ((b * 512 + kt * 64 + row) * 256) + h * 64 + (f4 - 64));
            float4 v = *(const float4*)src;
            uint32_t h0 = packh(v.x, v.y), h1 = packh(v.z, v.w);
            uint32_t l0 = packl(v.x, v.y, h0), l1 = packl(v.z, v.w, h1);
            *(uint2*)&Khi[row * QS + f4] = make_uint2(h0, h1);
            *(uint2*)&Klo[row * QS + f4] = make_uint2(l0, l1);
        }
        __syncthreads();

        float acc[2][2][4];
#pragma unroll
        for (int mi = 0; mi < 2; mi++)
#pragma unroll
            for (int ni = 0; ni < 2; ni++)
#pragma unroll
                for (int e = 0; e < 4; e++) acc[mi][ni][e] = 0.f;

#pragma unroll
        for (int ks = 0; ks < 8; ks++) {
            const int kb = ks * 16;
            uint32_t ah[2][4], al[2][4];
            const int ar = wm2 + (lane & 15);
            const int akk = kb + (lane >> 4) * 8;
#pragma unroll
            for (int mi = 0; mi < 2; mi++) {
                LDSM_X4(ah[mi], smem_u32(&Qhi[(ar + mi * 16) * QS + akk]));
                LDSM_X4(al[mi], smem_u32(&Qlo[(ar + mi * 16) * QS + akk]));
            }
            uint32_t bh[4], bl[4];
            const int nr  = (lane & 7) + ((lane >> 4) & 1) * 8;
            const int kk2 = kb + ((lane >> 3) & 1) * 8;
            LDSM_X4(bh, smem_u32(&Khi[(wn + nr) * QS + kk2]));
            LDSM_X4(bl, smem_u32(&Klo[(wn + nr) * QS + kk2]));
#pragma unroll
            for (int mi = 0; mi < 2; mi++)
#pragma unroll
                for (int ni = 0; ni < 2; ni++) {
                    MMA_BF16(acc[mi][ni], ah[mi], (&bh[ni * 2]));
                    MMA_BF16(acc[mi][ni], ah[mi], (&bl[ni * 2]));
                    MMA_BF16(acc[mi][ni], al[mi], (&bh[ni * 2]));
                }
        }

        // epilogue: dist -> e into Ssc
#pragma unroll
        for (int mi = 0; mi < 2; mi++) {
            const int i0 = wm2 + mi * 16 + g;
#pragma unroll
            for (int ni = 0; ni < 2; ni++) {
                const int j = kt * 64 + wn + ni * 8 + 2 * t;
                const float akj0 = aks[j], akj1 = aks[j + 1];
                float2 m0 = *(const float2*)&mrow[(size_t)i0 * 512 + j];
                float2 m1 = *(const float2*)&mrow[(size_t)(i0 + 8) * 512 + j];
                float d00 = aqs[i0]     + akj0 - 2.f * acc[mi][ni][0];
                float d01 = aqs[i0]     + akj1 - 2.f * acc[mi][ni][1];
                float d10 = aqs[i0 + 8] + akj0 - 2.f * acc[mi][ni][2];
                float d11 = aqs[i0 + 8] + akj1 - 2.f * acc[mi][ni][3];
                float2 e0 = make_float2(fexp(-d00) * 0.125f + m0.x,
                                        fexp(-d01) * 0.125f + m0.y);
                float2 e1 = make_float2(fexp(-d10) * 0.125f + m1.x,
                                        fexp(-d11) * 0.125f + m1.y);
                *(float2*)&Ssc[i0 * SC_STR + j]       = e0;
                *(float2*)&Ssc[(i0 + 8) * SC_STR + j] = e1;
            }
        }
    }
    __syncthreads();

    // ================= Phase B: softmax =================
    {
        const int row = tid >> 2, sub = tid & 3;
        float m = -3.0e38f;
        for (int k = sub; k < 512; k += 4) m = fmaxf(m, Ssc[row * SC_STR + k]);
        m = fmaxf(m, __shfl_xor_sync(~0u, m, 1));
        m = fmaxf(m, __shfl_xor_sync(~0u, m, 2));
        float s = 0.f;
        for (int k = sub; k < 512; k += 4) {
            float e = fexp(Ssc[row * SC_STR + k] - m);
            Ssc[row * SC_STR + k] = e;
            s += e;
        }
        s += __shfl_xor_sync(~0u, s, 1);
        s += __shfl_xor_sync(~0u, s, 2);
        if (sub == 0) invzs[row] = 1.f / s;
    }
    __syncthreads();

    // normalize + write probs
    {
        const size_t pbase = (((size_t)(b * 4 + h)) * 512 + q0) * 512;
#pragma unroll
        for (int u = 0; u < 32; u++) {
            int lin = u * 256 + tid;
            int i   = lin >> 7;
            int k4  = (lin & 127) << 2;
            float z = invzs[i];
            float4 p = *(float4*)&Ssc[i * SC_STR + k4];
            p.x *= z; p.y *= z; p.z *= z; p.w *= z;
            *(float4*)&Ssc[i * SC_STR + k4] = p;
            *(float4*)(probs + pbase + (size_t)i * 512 + k4) = p;
        }
    }

    // ================= Phase C: PV =================
    float am[2][2][4], ac2[2][2][4];
#pragma unroll
    for (int mi = 0; mi < 2; mi++)
#pragma unroll
        for (int ni = 0; ni < 2; ni++)
#pragma unroll
            for (int e = 0; e < 4; e++) { am[mi][ni][e] = 0.f; ac2[mi][ni][e] = 0.f; }

    for (int kt = 0; kt < 8; kt++) {
        __syncthreads();
#pragma unroll
        for (int u = 0; u < 4; u++) {
            int idx = u * 256 + tid;       // 0..1023
            int row = idx >> 4;            // s 0..63
            int d4  = (idx & 15) * 4;      // 0..60
            const size_t gsrc = ((size_t)(b * 512 + kt * 64 + row) * 256) + h * 64 + d4;
            float4 vm = *(const float4*)(g_mv + gsrc);
            float4 vc = *(const float4*)(g_cv + gsrc);
            uint32_t h0 = packh(vm.x, vm.y), h1 = packh(vm.z, vm.w);
            *(uint2*)&Vmh[row * VS + d4] = make_uint2(h0, h1);
            *(uint2*)&Vml[row * VS + d4] = make_uint2(packl(vm.x, vm.y, h0), packl(vm.z, vm.w, h1));
            uint32_t c0 = packh(vc.x, vc.y), c1 = packh(vc.z, vc.w);
            *(uint2*)&Vch[row * VS + d4] = make_uint2(c0, c1);
            *(uint2*)&Vcl[row * VS + d4] = make_uint2(packl(vc.x, vc.y, c0), packl(vc.z, vc.w, c1));
        }
        __syncthreads();

#pragma unroll
        for (int ks = 0; ks < 4; ks++) {
            const int k0 = kt * 64 + ks * 16;     // column base in Ssc
            const int s0 = ks * 16;               // row base in V smem
            // A frags from P (and P^2), bf16 hi/lo
            uint32_t ph[2][4], pl[2][4], qh[2][4], ql[2][4];
#pragma unroll
            for (int mi = 0; mi < 2; mi++) {
                const int r0 = wm2 + mi * 16 + g;
                float2 x0 = *(const float2*)&Ssc[r0 * SC_STR + k0 + 2 * t];
                float2 x1 = *(const float2*)&Ssc[r0 * SC_STR + k0 + 2 * t + 8];
                float2 x2 = *(const float2*)&Ssc[(r0 + 8) * SC_STR + k0 + 2 * t];
                float2 x3 = *(const float2*)&Ssc[(r0 + 8) * SC_STR + k0 + 2 * t + 8];
                // reg order: a0=(g,2t), a1=(g+8,2t), a2=(g,2t+8), a3=(g+8,2t+8)
                ph[mi][0] = packh(x0.x, x0.y); pl[mi][0] = packl(x0.x, x0.y, ph[mi][0]);
                ph[mi][1] = packh(x2.x, x2.y); pl[mi][1] = packl(x2.x, x2.y, ph[mi][1]);
                ph[mi][2] = packh(x1.x, x1.y); pl[mi][2] = packl(x1.x, x1.y, ph[mi][2]);
                ph[mi][3] = packh(x3.x, x3.y); pl[mi][3] = packl(x3.x, x3.y, ph[mi][3]);
                float2 s0f = make_float2(x0.x * x0.x, x0.y * x0.y);
                float2 s1f = make_float2(x1.x * x1.x, x1.y * x1.y);
                float2 s2f = make_float2(x2.x * x2.x, x2.y * x2.y);
                float2 s3f = make_float2(x3.x * x3.x, x3.y * x3.y);
                qh[mi][0] = packh(s0f.x, s0f.y); ql[mi][0] = packl(s0f.x, s0f.y, qh[mi][0]);
                qh[mi][1] = packh(s2f.x, s2f.y); ql[mi][1] = packl(s2f.x, s2f.y, qh[mi][1]);
                qh[mi][2] = packh(s1f.x, s1f.y); ql[mi][2] = packl(s1f.x, s1f.y, qh[mi][2]);
                qh[mi][3] = packh(s3f.x, s3f.y); ql[mi][3] = packl(s3f.x, s3f.y, qh[mi][3]);
            }
            // B frags via ldmatrix.trans (V stored [s][d])
            uint32_t bmh[4], bml[4], bch[4], bcl[4];
            const int sr = (lane & 7) + ((lane >> 3) & 1) * 8;
            const int d8 = (lane >> 4) * 8;
            const int vbase = (s0 + sr) * VS + wn + d8;
            LDSM_X4_T(bmh, smem_u32(&Vmh[vbase]));
            LDSM_X4_T(bml, smem_u32(&Vml[vbase]));
            LDSM_X4_T(bch, smem_u32(&Vch[vbase]));
            LDSM_X4_T(bcl, smem_u32(&Vcl[vbase]));
#pragma unroll
            for (int mi = 0; mi < 2; mi++)
#pragma unroll
                for (int ni = 0; ni < 2; ni++) {
                    MMA_BF16(am[mi][ni],  ph[mi], (&bmh[ni * 2]));
                    MMA_BF16(am[mi][ni],  ph[mi], (&bml[ni * 2]));
                    MMA_BF16(am[mi][ni],  pl[mi], (&bmh[ni * 2]));
                    MMA_BF16(ac2[mi][ni], qh[mi], (&bch[ni * 2]));
                    MMA_BF16(ac2[mi][ni], qh[mi], (&bcl[ni * 2]));
                    MMA_BF16(ac2[mi][ni], ql[mi], (&bch[ni * 2]));
                }
        }
    }

    // ---- store ctx directly as bf16 hi/lo split ----
#pragma unroll
    for (int mi = 0; mi < 2; mi++) {
#pragma unroll
        for (int ni = 0; ni < 2; ni++) {
            const int row = q0 + wm2 + mi * 16 + g;
            const int col = h * 64 + wn + ni * 8 + 2 * t;
            const size_t i0 = ((size_t)(b * 512 + row)) * 256 + col;
            const size_t i1 = ((size_t)(b * 512 + row + 8)) * 256 + col;
            uint32_t mh0 = packh(am[mi][ni][0], am[mi][ni][1]);
            uint32_t mh1 = packh(am[mi][ni][2], am[mi][ni][3]);
            *(uint32_t*)&g_cmh[i0] = mh0;
            *(uint32_t*)&g_cml[i0] = packl(am[mi][ni][0], am[mi][ni][1], mh0);
            *(uint32_t*)&g_cmh[i1] = mh1;
            *(uint32_t*)&g_cml[i1] = packl(am[mi][ni][2], am[mi][ni][3], mh1);
            uint32_t ch0 = packh(ac2[mi][ni][0], ac2[mi][ni][1]);
            uint32_t ch1 = packh(ac2[mi][ni][2], ac2[mi][ni][3]);
            *(uint32_t*)&g_cch[i0] = ch0;
            *(uint32_t*)&g_ccl[i0] = packl(ac2[mi][ni][0], ac2[mi][ni][1], ch0);
            *(uint32_t*)&g_cch[i1] = ch1;
            *(uint32_t*)&g_ccl[i1] = packl(ac2[mi][ni][2], ac2[mi][ni][3], ch1);
        }
    }
}

// ---------------------------------------------------------------------------
// LayerNorm: out = lw * norm(D + X) + lb
// ---------------------------------------------------------------------------
__global__ __launch_bounds__(256)
void ln_kernel(const float* __restrict__ D, const float* __restrict__ X,
               const float* __restrict__ lw, const float* __restrict__ lb,
               float* __restrict__ O)
{
    __shared__ float red[16];
    const int r = blockIdx.x, t = threadIdx.x;
    const size_t base = (size_t)r * 256;
    float v = D[base + t] + X[base + t];
    float s1 = v, s2 = v * v;
#pragma unroll
    for (int o = 16; o; o >>= 1) {
        s1 += __shfl_xor_sync(~0u, s1, o);
        s2 += __shfl_xor_sync(~0u, s2, o);
    }
    const int wid = t >> 5, lane = t & 31;
    if (!lane) { red[wid] = s1; red[8 + wid] = s2; }
    __syncthreads();
    float S1 = 0.f, S2 = 0.f;
#pragma unroll
    for (int i = 0; i < 8; i++) { S1 += red[i]; S2 += red[8 + i]; }
    float u   = S1 * (1.f / 256.f);
    float var = fmaxf(S2 * (1.f / 256.f) - u * u, 0.f);
    float y = fmaf(lw[t], (v - u) * rsqrtf(var + 1e-12f), lb[t]);
    O[base + t] = y;
}

// ---------------------------------------------------------------------------
// kernel_launch
// ---------------------------------------------------------------------------
extern "C" void kernel_launch(void* const* d_in, const int* in_sizes, int n_in,
                              void* d_out, int out_size)
{
    (void)in_sizes; (void)n_in; (void)out_size;
    const float* in_mean = (const float*)d_in[0];
    const float* in_cov  = (const float*)d_in[1];
    const float* mask    = (const float*)d_in[2];
    const float* W[8]    = { (const float*)d_in[3],  (const float*)d_in[5],
                             (const float*)d_in[7],  (const float*)d_in[9],
                             (const float*)d_in[11], (const float*)d_in[13],
                             (const float*)d_in[15], (const float*)d_in[17] };
    const float* bia[8]  = { (const float*)d_in[4],  (const float*)d_in[6],
                             (const float*)d_in[8],  (const float*)d_in[10],
                             (const float*)d_in[12], (const float*)d_in[14],
                             (const float*)d_in[16], (const float*)d_in[18] };
    const float* lw  = (const float*)d_in[19];
    const float* lb  = (const float*)d_in[20];
    float* out = (float*)d_out;

    float *mq, *mk, *mv, *sq, *sk, *cv, *dm, *dc, *aq, *ak;
    cudaGetSymbolAddress((void**)&mq,   g_mq);
    cudaGetSymbolAddress((void**)&mk,   g_mk);
    cudaGetSymbolAddress((void**)&mv,   g_mv);
    cudaGetSymbolAddress((void**)&sq,   g_sq);
    cudaGetSymbolAddress((void**)&sk,   g_sk);
    cudaGetSymbolAddress((void**)&cv,   g_cv);
    cudaGetSymbolAddress((void**)&dm,   g_dm);
    cudaGetSymbolAddress((void**)&dc,   g_dc);
    cudaGetSymbolAddress((void**)&aq,   g_aq);
    cudaGetSymbolAddress((void**)&ak,   g_ak);

    __nv_bfloat16 *xmh, *xml, *xch, *xcl, *cmh, *cml, *cch, *ccl, *wh, *wl;
    cudaGetSymbolAddress((void**)&xmh, g_xmh);
    cudaGetSymbolAddress((void**)&xml, g_xml);
    cudaGetSymbolAddress((void**)&xch, g_xch);
    cudaGetSymbolAddress((void**)&xcl, g_xcl);
    cudaGetSymbolAddress((void**)&cmh, g_cmh);
    cudaGetSymbolAddress((void**)&cml, g_cml);
    cudaGetSymbolAddress((void**)&cch, g_cch);
    cudaGetSymbolAddress((void**)&ccl, g_ccl);
    cudaGetSymbolAddress((void**)&wh,  g_wh);
    cudaGetSymbolAddress((void**)&wl,  g_wl);

    cudaFuncSetAttribute(attn_tc, cudaFuncAttributeMaxDynamicSharedMemorySize,
                         ATT_SMEM_BYTES);

    // ---- bf16 hi/lo conversions ----
    split_bf16<<<MAT / 4 / 256, 256>>>(in_mean, xmh, xml, MAT / 4);
    split_bf16<<<MAT / 4 / 256, 256>>>(in_cov,  xch, xcl, MAT / 4);
    for (int i = 0; i < 8; i++)
        split_bf16<<<WSZ / 4 / 256, 256>>>(W[i], wh + (size_t)i * WSZ,
                                           wl + (size_t)i * WSZ, WSZ / 4);

    dim3 gg(MROWS / 128, 2);

    // ---- projections (HMMA) ----
    gemm_hmma<<<gg, 256>>>(xmh, xml, wh + 0*WSZ, wl + 0*WSZ, bia[0], mq, 0);
    gemm_hmma<<<gg, 256>>>(xmh, xml, wh + 1*WSZ, wl + 1*WSZ, bia[1], mk, 0);
    gemm_hmma<<<gg, 256>>>(xmh, xml, wh + 2*WSZ, wl + 2*WSZ, bia[2], mv, 0);
    gemm_hmma<<<gg, 256>>>(xch, xcl, wh + 3*WSZ, wl + 3*WSZ, bia[3], sq, 2);
    gemm_hmma<<<gg, 256>>>(xch, xcl, wh + 4*WSZ, wl + 4*WSZ, bia[4], sk, 2);
    gemm_hmma<<<gg, 256>>>(xch, xcl, wh + 5*WSZ, wl + 5*WSZ, bia[5], cv, 1);

    // ---- row scalars ----
    rowsum_kernel<<<NROW / 8, 256>>>(mq, sq, aq);
    rowsum_kernel<<<NROW / 8, 256>>>(mk, sk, ak);

    // ---- tensor-core attention (probs -> out + 2*MAT; ctx -> bf16 splits) ----
    attn_tc<<<dim3(SS / 64, NH, BB), 256, ATT_SMEM_BYTES>>>(mask, out + 2 * (size_t)MAT);

    // ---- output denses (HMMA, reading attn-produced splits) ----
    gemm_hmma<<<gg, 256>>>(cmh, cml, wh + 6*WSZ, wl + 6*WSZ, bia[6], dm, 0);
    gemm_hmma<<<gg, 256>>>(cch, ccl, wh + 7*WSZ, wl + 7*WSZ, bia[7], dc, 0);

    // ---- residual + layernorm ----
    ln_kernel<<<MROWS, 256>>>(dm, in_mean, lw, lb, out);
    ln_kernel<<<MROWS, 256>>>(dc, in_cov,  lw, lb, out + (size_t)MAT);
}